// round 7
// baseline (speedup 1.0000x reference)
#include <cuda_runtime.h>

#define D_      64
#define K_      16
#define N_      65536
#define P_      2
#define NOISEF  0.1f
#define LOG2PI_F 1.83787706640934534f

#define NBLK    296          // 2 CTAs x 148 SMs
#define TROWS   32
#define NTILES  (N_ / TROWS) // 2048
#define WST     20           // padded row stride for 64x16 arrays (16B-aligned float4)

__device__ float    g_Cf[D_ * D_];
__device__ double   g_loss;
__device__ unsigned g_done;

typedef unsigned long long u64;

__device__ __forceinline__ void ffma2(u64& acc, u64 a, u64 b) {
    asm("fma.rn.f32x2 %0, %1, %2, %3;" : "=l"(acc) : "l"(a), "l"(b), "l"(acc));
}
__device__ __forceinline__ u64 swap2(u64 x) {
    return (x >> 32) | (x << 32);
}
__device__ __forceinline__ void cpasync16(unsigned smem, const void* g) {
    asm volatile("cp.async.cg.shared.global [%0], [%1], 16;\n" :: "r"(smem), "l"(g));
}
__device__ __forceinline__ void cp_commit() {
    asm volatile("cp.async.commit_group;\n" ::: "memory");
}
__device__ __forceinline__ void cp_wait2() {
    asm volatile("cp.async.wait_group 2;\n" ::: "memory");
}
__device__ __forceinline__ void cp_wait0() {
    asm volatile("cp.async.wait_group 0;\n" ::: "memory");
}

// ---------------------------------------------------------------------------
// Kernel 1: C = x^T x. 296 persistent blocks, 4-slot cp.async pipeline
// (2 full tiles in flight), swapped-pair packed-FMA outer product.
// ---------------------------------------------------------------------------
__global__ __launch_bounds__(256, 2) void k_xtx(const float* __restrict__ x) {
    __shared__ __align__(16) float sx[4][TROWS * 64];

    const int tid = threadIdx.x;
    const int g   = tid >> 6;
    const int t   = tid & 63;
    const int ti  = (t >> 3) << 3;
    const int tj  = (t & 7) << 3;

    u64 accN[4][4], accS[4][4];
#pragma unroll
    for (int u = 0; u < 4; ++u)
#pragma unroll
        for (int v = 0; v < 4; ++v) { accN[u][v] = 0ull; accS[u][v] = 0ull; }

    unsigned sb[4];
#pragma unroll
    for (int s = 0; s < 4; ++s)
        sb[s] = (unsigned)__cvta_generic_to_shared(&sx[s][0]);

    // prologue: prefetch 3 tiles
#pragma unroll
    for (int s = 0; s < 3; ++s) {
        int tt = blockIdx.x + s * NBLK;
        if (tt < NTILES) {
            const float4* g4 = reinterpret_cast<const float4*>(x + (long long)tt * TROWS * 64);
            cpasync16(sb[s] + tid * 16, g4 + tid);
            cpasync16(sb[s] + (tid + 256) * 16, g4 + tid + 256);
        }
        cp_commit();
    }

    int sidx = 0;
    for (int tile = blockIdx.x; tile < NTILES; tile += NBLK) {
        cp_wait2();               // oldest (this tile) complete
        __syncthreads();          // everyone done with slot (sidx-1) & sees data

        int pf = tile + 3 * NBLK;
        int ps = (sidx + 3) & 3;
        if (pf < NTILES) {
            const float4* g4 = reinterpret_cast<const float4*>(x + (long long)pf * TROWS * 64);
            cpasync16(sb[ps] + tid * 16, g4 + tid);
            cpasync16(sb[ps] + (tid + 256) * 16, g4 + tid + 256);
        }
        cp_commit();

        const float* rb = &sx[sidx][0] + g * (8 * 64);
#pragma unroll
        for (int rr = 0; rr < 8; ++rr) {
            const ulonglong2* xiv = reinterpret_cast<const ulonglong2*>(rb + rr * 64 + ti);
            ulonglong2 A0 = xiv[0], A1 = xiv[1];
            u64 xi2[4] = {A0.x, A0.y, A1.x, A1.y};
            const u64* xjv = reinterpret_cast<const u64*>(rb + rr * 64 + tj);
            u64 xj2[4], xjs[4];
#pragma unroll
            for (int v = 0; v < 4; ++v) { xj2[v] = xjv[v]; xjs[v] = swap2(xj2[v]); }
#pragma unroll
            for (int u = 0; u < 4; ++u)
#pragma unroll
                for (int v = 0; v < 4; ++v) {
                    ffma2(accN[u][v], xi2[u], xj2[v]);
                    ffma2(accS[u][v], xi2[u], xjs[v]);
                }
        }
        sidx = (sidx + 1) & 3;
    }
    cp_wait0();
    __syncthreads();

    // unscramble + reduce the 4 groups into sx[0..1] (4096 floats)
    float* red = &sx[0][0];
    for (int gg = 0; gg < 4; ++gg) {
        if (g == gg) {
#pragma unroll
            for (int u = 0; u < 4; ++u)
#pragma unroll
                for (int v = 0; v < 4; ++v) {
                    int r0 = ti + 2 * u, c0 = tj + 2 * v;
                    float nlo = __uint_as_float((unsigned)(accN[u][v] & 0xffffffffull));
                    float nhi = __uint_as_float((unsigned)(accN[u][v] >> 32));
                    float slo = __uint_as_float((unsigned)(accS[u][v] & 0xffffffffull));
                    float shi = __uint_as_float((unsigned)(accS[u][v] >> 32));
                    if (gg == 0) {
                        red[r0 * 64 + c0]           = nlo;
                        red[(r0 + 1) * 64 + c0 + 1] = nhi;
                        red[r0 * 64 + c0 + 1]       = slo;
                        red[(r0 + 1) * 64 + c0]     = shi;
                    } else {
                        red[r0 * 64 + c0]           += nlo;
                        red[(r0 + 1) * 64 + c0 + 1] += nhi;
                        red[r0 * 64 + c0 + 1]       += slo;
                        red[(r0 + 1) * 64 + c0]     += shi;
                    }
                }
        }
        __syncthreads();
    }
#pragma unroll
    for (int i = 0; i < 16; ++i)
        atomicAdd(&g_Cf[tid + 256 * i], red[tid + 256 * i]);
}

// ---------------------------------------------------------------------------
// Kernel 2: one block per (a,p). Permutation-free Woodbury:
//   pos = perm^-1 ; Wm[o] = W[o] * [pos[o] >= m]   (original index space)
//   G = 0.1 I + Wm^T Wm ; Z = C @ Wm ; T = Wm^T Z
//   w = W[perm_i] ; b = Ginv w ; v = 0.1 (1 + w.b)
//   Q = C[pi,pi] - 2 b.Z[pi] + b^T T b
// All inner loops full-unrolled, bank-conflict-free (pad 65 / 20).
// ---------------------------------------------------------------------------
__global__ __launch_bounds__(256) void k_pairs(const float* __restrict__ W,
                                               const int* __restrict__ perms,
                                               float* __restrict__ out) {
    __shared__ __align__(16) float sC[D_ * 65];
    __shared__ __align__(16) float sW[D_ * WST];
    __shared__ __align__(16) float sWm[D_ * WST];
    __shared__ __align__(16) float sZ[D_ * WST];
    __shared__ float sT[K_ * K_];
    __shared__ float sG[K_ * K_];
    __shared__ float sGi[K_ * K_];
    __shared__ int   sperm[D_];
    __shared__ int   spos[D_];
    __shared__ float sred[2];
    __shared__ int   slast;

    const int tid = threadIdx.x;
    const int a   = blockIdx.x >> 1;
    const int m   = a + 1;
    const int* perm = perms + (a * P_ + (blockIdx.x & 1)) * D_;

#pragma unroll
    for (int i = 0; i < 16; ++i) {
        int idx = tid + 256 * i;
        sC[(idx >> 6) * 65 + (idx & 63)] = g_Cf[idx];
    }
    if (tid < D_) sperm[tid] = perm[tid];
#pragma unroll
    for (int i = 0; i < 4; ++i) {
        int idx = tid + 256 * i;
        sW[(idx >> 4) * WST + (idx & 15)] = W[idx];
    }
    __syncthreads();
    if (tid < D_) spos[sperm[tid]] = tid;
    __syncthreads();
#pragma unroll
    for (int i = 0; i < 4; ++i) {
        int idx = tid + 256 * i;
        int o = idx >> 4, k = idx & 15;
        sWm[o * WST + k] = (spos[o] >= m) ? sW[o * WST + k] : 0.f;
    }
    __syncthreads();

    // G: one element per thread
    const int gk = tid >> 4, gl = tid & 15;
    {
        float s = (gk == gl) ? NOISEF : 0.f;
#pragma unroll
        for (int o = 0; o < D_; ++o)
            s += sWm[o * WST + gk] * sWm[o * WST + gl];
        sG[gk * K_ + gl] = s;
    }
    // Z: thread (o = tid&63, lb = (tid>>6)*4)
    {
        const int o = tid & 63, lb = (tid >> 6) << 2;
        float z0 = 0.f, z1 = 0.f, z2 = 0.f, z3 = 0.f;
#pragma unroll
        for (int j = 0; j < D_; ++j) {
            float c = sC[o * 65 + j];
            const float4 wv = *reinterpret_cast<const float4*>(sWm + j * WST + lb);
            z0 += c * wv.x; z1 += c * wv.y; z2 += c * wv.z; z3 += c * wv.w;
        }
        *reinterpret_cast<float4*>(sZ + o * WST + lb) = make_float4(z0, z1, z2, z3);
    }
    __syncthreads();

    if (tid < 32) {
        // warp 0: shuffle Jordan inversion of 16x16 SPD G
        const int lane = tid;
        float col[K_];
#pragma unroll
        for (int r = 0; r < K_; ++r)
            col[r] = (lane < K_) ? sG[r * K_ + lane]
                                 : ((r == lane - K_) ? 1.f : 0.f);
#pragma unroll
        for (int k = 0; k < K_; ++k) {
            float pv = __shfl_sync(0xffffffffu, col[k], k);
            float ip = 1.0f / pv;
            float ck = col[k];
#pragma unroll
            for (int r = 0; r < K_; ++r) {
                if (r != k) {
                    float mr = __shfl_sync(0xffffffffu, col[r], k) * ip;
                    col[r] -= mr * ck;
                }
            }
        }
        float own = 1.f;
#pragma unroll
        for (int r = 0; r < K_; ++r)
            if (r == lane) own = col[r];
        float oinv = 1.0f / own;
#pragma unroll
        for (int r = 0; r < K_; ++r) {
            float di = __shfl_sync(0xffffffffu, oinv, r);
            if (lane >= K_) sGi[r * K_ + (lane - K_)] = col[r] * di;
        }
    } else {
        // warps 1-7: T (256 items over 224 threads)
        for (int it = tid - 32; it < 256; it += 224) {
            int k = it >> 4, l = it & 15;
            float s = 0.f;
#pragma unroll
            for (int o = 0; o < D_; ++o)
                s += sWm[o * WST + k] * sZ[o * WST + l];
            sT[k * K_ + l] = s;
        }
    }
    __syncthreads();

    // per-row terms
    float term = 0.f;
    if (tid < m) {
        const int pi = sperm[tid];
        float w[K_], b[K_];
#pragma unroll
        for (int k4 = 0; k4 < K_; k4 += 4) {
            const float4 wv = *reinterpret_cast<const float4*>(sW + pi * WST + k4);
            w[k4] = wv.x; w[k4 + 1] = wv.y; w[k4 + 2] = wv.z; w[k4 + 3] = wv.w;
        }
#pragma unroll
        for (int l = 0; l < K_; ++l) {
            float s = 0.f;
#pragma unroll
            for (int k = 0; k < K_; ++k) s += sGi[l * K_ + k] * w[k];
            b[l] = s;
        }
        float wb = 0.f, by = 0.f, btb = 0.f;
#pragma unroll
        for (int k = 0; k < K_; ++k) {
            wb += w[k] * b[k];
            by += b[k] * sZ[pi * WST + k];
            float s = 0.f;
#pragma unroll
            for (int l = 0; l < K_; ++l) s += sT[k * K_ + l] * b[l];
            btb += b[k] * s;
        }
        float v = NOISEF * (1.f + wb);
        float Q = sC[pi * 65 + pi] - 2.f * by + btb;
        term = -0.5f * logf(v) - 0.5f * LOG2PI_F - 0.5f * Q / (v * (float)N_);
    }
    if (tid < 64) {
#pragma unroll
        for (int o = 16; o > 0; o >>= 1)
            term += __shfl_xor_sync(0xffffffffu, term, o);
        if ((tid & 31) == 0) sred[tid >> 5] = term;
    }
    __syncthreads();
    if (tid == 0) {
        atomicAdd(&g_loss, (double)(sred[0] + sred[1]) / ((double)P_ * (double)m));
        __threadfence();
        unsigned d = atomicAdd(&g_done, 1u);
        slast = (d == (unsigned)(D_ * P_ - 1)) ? 1 : 0;
    }
    __syncthreads();

    if (slast) {
        for (int i = tid; i < D_ * D_; i += 256) g_Cf[i] = 0.f;
        if (tid == 0) {
            out[0] = -(float)g_loss;
            g_loss = 0.0;
            g_done = 0u;
        }
    }
}

extern "C" void kernel_launch(void* const* d_in, const int* in_sizes, int n_in,
                              void* d_out, int out_size) {
    const float* x     = (const float*)d_in[0];
    const float* W     = (const float*)d_in[1];
    const int*   perms = (const int*)d_in[2];
    (void)in_sizes; (void)n_in; (void)out_size;

    k_xtx<<<NBLK, 256>>>(x);
    k_pairs<<<D_ * P_, 256>>>(W, perms, (float*)d_out);
}

// round 8
// speedup vs baseline: 1.7117x; 1.7117x over previous
#include <cuda_runtime.h>

#define D_      64
#define K_      16
#define N_      65536
#define P_      2
#define NOISEF  0.1f
#define LOG2PI_F 1.83787706640934534f

#define NBLK    296          // 2 CTAs x 148 SMs, all co-resident
#define TROWS   32
#define NTILES  (N_ / TROWS) // 2048
#define SXST    68           // padded row stride (floats) for the x tile
#define WST     20           // padded row stride for 64x16 arrays

__device__ float    g_Cf[D_ * D_];
__device__ double   g_loss;
__device__ unsigned g_done;      // xtx-phase completion counter
__device__ unsigned g_done2;     // pairs-phase completion counter

__device__ __forceinline__ void cpasync16(unsigned smem, const void* g) {
    asm volatile("cp.async.cg.shared.global [%0], [%1], 16;\n" :: "r"(smem), "l"(g));
}
__device__ __forceinline__ void cp_commit() {
    asm volatile("cp.async.commit_group;\n" ::: "memory");
}
__device__ __forceinline__ void cp_wait1() {
    asm volatile("cp.async.wait_group 1;\n" ::: "memory");
}
__device__ __forceinline__ unsigned cvt_tf32(float f) {
    unsigned r;
    asm("cvt.rna.tf32.f32 %0, %1;" : "=r"(r) : "f"(f));
    return r;
}
__device__ __forceinline__ void mma_tf32(float& d0, float& d1, float& d2, float& d3,
                                         unsigned a0, unsigned a1, unsigned a2, unsigned a3,
                                         unsigned b0, unsigned b1) {
    asm("mma.sync.aligned.m16n8k8.row.col.f32.tf32.tf32.f32 "
        "{%0,%1,%2,%3}, {%4,%5,%6,%7}, {%8,%9}, {%0,%1,%2,%3};"
        : "+f"(d0), "+f"(d1), "+f"(d2), "+f"(d3)
        : "r"(a0), "r"(a1), "r"(a2), "r"(a3), "r"(b0), "r"(b1));
}

struct XtxSmem {
    float sx[3][TROWS * SXST];   // 3-slot cp.async pipeline, padded rows
};
struct PairsSmem {
    float sC[D_ * 65];
    float sW[D_ * WST];
    float sWm[D_ * WST];
    float sZ[D_ * WST];
    float sT[K_ * K_];
    float sG[K_ * K_];
    float sGi[K_ * K_];
    int   sperm[D_];
    int   spos[D_];
    float sred[2];
    int   slast;
};
#define SMEM_BYTES (sizeof(PairsSmem) > sizeof(XtxSmem) ? sizeof(PairsSmem) : sizeof(XtxSmem))

// ---------------------------------------------------------------------------
// Fused persistent kernel.
// Phase 1 (all 296 blocks): C = x^T x via tf32 mma.sync. Each block streams
// its grid-stride share of 32-row tiles through a 3-slot cp.async pipeline;
// 8 warps tile the 64x64 output as (4 m-strips) x (2 n-halves); accumulators
// persist across tiles; one float-atomic flush at the end.
// Phase 2 (blocks 0..127): after a device-wide counter spin, the Woodbury
// per-(a,p) evaluation (unchanged from R7). Last block finalizes + resets.
// ---------------------------------------------------------------------------
__global__ __launch_bounds__(256, 2) void k_fused(const float* __restrict__ x,
                                                  const float* __restrict__ W,
                                                  const int* __restrict__ perms,
                                                  float* __restrict__ out) {
    __shared__ __align__(16) unsigned char smem_u[SMEM_BYTES];
    XtxSmem& xs = *reinterpret_cast<XtxSmem*>(smem_u);

    const int tid = threadIdx.x;

    // ---------------- Phase 1: tf32 MMA x^T x ----------------
    {
        const int w    = tid >> 5;
        const int lane = tid & 31;
        const int gid  = lane >> 2;       // 0..7
        const int tig  = lane & 3;        // 0..3
        const int ms   = (w >> 1) << 4;   // m-strip base: 0,16,32,48
        const int nh   = (w & 1) << 5;    // n-half base: 0,32

        float acc[4][4];
#pragma unroll
        for (int t = 0; t < 4; ++t)
#pragma unroll
            for (int q = 0; q < 4; ++q) acc[t][q] = 0.f;

        unsigned sb[3];
#pragma unroll
        for (int s = 0; s < 3; ++s)
            sb[s] = (unsigned)__cvta_generic_to_shared(&xs.sx[s][0]);

        // cp.async staging: 512 float4 per tile; f4idx -> row=f4idx>>4, seg=f4idx&15
        const int r0s = tid >> 4, g0s = tid & 15;               // first 256
        const int r1s = (tid + 256) >> 4, g1s = tid & 15;       // second 256
        const unsigned so0 = (unsigned)(r0s * SXST * 4 + g0s * 16);
        const unsigned so1 = (unsigned)(r1s * SXST * 4 + g1s * 16);

        // prologue: prefetch tiles bid, bid+NBLK into slots 0,1
#pragma unroll
        for (int s = 0; s < 2; ++s) {
            int tt = blockIdx.x + s * NBLK;
            if (tt < NTILES) {
                const float4* g4 = reinterpret_cast<const float4*>(x + (long long)tt * TROWS * 64);
                cpasync16(sb[s] + so0, g4 + tid);
                cpasync16(sb[s] + so1, g4 + tid + 256);
            }
            cp_commit();
        }

        int sidx = 0;
        for (int tile = blockIdx.x; tile < NTILES; tile += NBLK) {
            cp_wait1();
            __syncthreads();

            int pf = tile + 2 * NBLK;
            int ps = sidx + 2; if (ps >= 3) ps -= 3;
            if (pf < NTILES) {
                const float4* g4 = reinterpret_cast<const float4*>(x + (long long)pf * TROWS * 64);
                cpasync16(sb[ps] + so0, g4 + tid);
                cpasync16(sb[ps] + so1, g4 + tid + 256);
            }
            cp_commit();

            const float* sxt = &xs.sx[sidx][0];
#pragma unroll
            for (int ks = 0; ks < 4; ++ks) {
                const float* r0 = sxt + (ks * 8 + tig) * SXST;
                const float* r4 = r0 + 4 * SXST;
                unsigned a0 = cvt_tf32(r0[ms + gid]);
                unsigned a1 = cvt_tf32(r0[ms + gid + 8]);
                unsigned a2 = cvt_tf32(r4[ms + gid]);
                unsigned a3 = cvt_tf32(r4[ms + gid + 8]);
#pragma unroll
                for (int t = 0; t < 4; ++t) {
                    int n0 = nh + t * 8;
                    unsigned b0 = cvt_tf32(r0[n0 + gid]);
                    unsigned b1 = cvt_tf32(r4[n0 + gid]);
                    mma_tf32(acc[t][0], acc[t][1], acc[t][2], acc[t][3],
                             a0, a1, a2, a3, b0, b1);
                }
            }
            sidx += 1; if (sidx >= 3) sidx -= 3;
        }

        // flush accumulators (fragment layout: rows ms+gid / +8, cols n0+2tig / +1)
#pragma unroll
        for (int t = 0; t < 4; ++t) {
            int c0 = nh + t * 8 + 2 * tig;
            atomicAdd(&g_Cf[(ms + gid) * 64 + c0],     acc[t][0]);
            atomicAdd(&g_Cf[(ms + gid) * 64 + c0 + 1], acc[t][1]);
            atomicAdd(&g_Cf[(ms + gid + 8) * 64 + c0],     acc[t][2]);
            atomicAdd(&g_Cf[(ms + gid + 8) * 64 + c0 + 1], acc[t][3]);
        }
        __threadfence();
        __syncthreads();
        if (tid == 0) atomicAdd(&g_done, 1u);
    }

    // ---------------- Phase 2: Woodbury pairs (blocks 0..127) ----------------
    if (blockIdx.x >= D_ * P_) return;

    if (tid == 0) {
        while (*((volatile unsigned*)&g_done) < NBLK) __nanosleep(32);
        __threadfence();
    }
    __syncthreads();     // also fences the smem union switch

    PairsSmem& psm = *reinterpret_cast<PairsSmem*>(smem_u);

    const int a = blockIdx.x >> 1;
    const int m = a + 1;
    const int* perm = perms + (a * P_ + (blockIdx.x & 1)) * D_;

#pragma unroll
    for (int i = 0; i < 16; ++i) {
        int idx = tid + 256 * i;
        psm.sC[(idx >> 6) * 65 + (idx & 63)] = g_Cf[idx];
    }
    if (tid < D_) psm.sperm[tid] = perm[tid];
#pragma unroll
    for (int i = 0; i < 4; ++i) {
        int idx = tid + 256 * i;
        psm.sW[(idx >> 4) * WST + (idx & 15)] = W[idx];
    }
    __syncthreads();
    if (tid < D_) psm.spos[psm.sperm[tid]] = tid;
    __syncthreads();
#pragma unroll
    for (int i = 0; i < 4; ++i) {
        int idx = tid + 256 * i;
        int o = idx >> 4, k = idx & 15;
        psm.sWm[o * WST + k] = (psm.spos[o] >= m) ? psm.sW[o * WST + k] : 0.f;
    }
    __syncthreads();

    // G: one element per thread
    const int gk = tid >> 4, gl = tid & 15;
    {
        float s = (gk == gl) ? NOISEF : 0.f;
#pragma unroll
        for (int o = 0; o < D_; ++o)
            s += psm.sWm[o * WST + gk] * psm.sWm[o * WST + gl];
        psm.sG[gk * K_ + gl] = s;
    }
    // Z = C @ Wm
    {
        const int o = tid & 63, lb = (tid >> 6) << 2;
        float z0 = 0.f, z1 = 0.f, z2 = 0.f, z3 = 0.f;
#pragma unroll
        for (int j = 0; j < D_; ++j) {
            float c = psm.sC[o * 65 + j];
            const float4 wv = *reinterpret_cast<const float4*>(psm.sWm + j * WST + lb);
            z0 += c * wv.x; z1 += c * wv.y; z2 += c * wv.z; z3 += c * wv.w;
        }
        *reinterpret_cast<float4*>(psm.sZ + o * WST + lb) = make_float4(z0, z1, z2, z3);
    }
    __syncthreads();

    if (tid < 32) {
        // warp 0: shuffle Jordan inversion of 16x16 SPD G
        const int lane = tid;
        float col[K_];
#pragma unroll
        for (int r = 0; r < K_; ++r)
            col[r] = (lane < K_) ? psm.sG[r * K_ + lane]
                                 : ((r == lane - K_) ? 1.f : 0.f);
#pragma unroll
        for (int k = 0; k < K_; ++k) {
            float pv = __shfl_sync(0xffffffffu, col[k], k);
            float ip = 1.0f / pv;
            float ck = col[k];
#pragma unroll
            for (int r = 0; r < K_; ++r) {
                if (r != k) {
                    float mr = __shfl_sync(0xffffffffu, col[r], k) * ip;
                    col[r] -= mr * ck;
                }
            }
        }
        float own = 1.f;
#pragma unroll
        for (int r = 0; r < K_; ++r)
            if (r == lane) own = col[r];
        float oinv = 1.0f / own;
#pragma unroll
        for (int r = 0; r < K_; ++r) {
            float di = __shfl_sync(0xffffffffu, oinv, r);
            if (lane >= K_) psm.sGi[r * K_ + (lane - K_)] = col[r] * di;
        }
    } else {
        // warps 1-7: T = Wm^T Z
        for (int it = tid - 32; it < 256; it += 224) {
            int k = it >> 4, l = it & 15;
            float s = 0.f;
#pragma unroll
            for (int o = 0; o < D_; ++o)
                s += psm.sWm[o * WST + k] * psm.sZ[o * WST + l];
            psm.sT[k * K_ + l] = s;
        }
    }
    __syncthreads();

    // per-row terms
    float term = 0.f;
    if (tid < m) {
        const int pi = psm.sperm[tid];
        float w[K_], b[K_];
#pragma unroll
        for (int k4 = 0; k4 < K_; k4 += 4) {
            const float4 wv = *reinterpret_cast<const float4*>(psm.sW + pi * WST + k4);
            w[k4] = wv.x; w[k4 + 1] = wv.y; w[k4 + 2] = wv.z; w[k4 + 3] = wv.w;
        }
#pragma unroll
        for (int l = 0; l < K_; ++l) {
            float s = 0.f;
#pragma unroll
            for (int k = 0; k < K_; ++k) s += psm.sGi[l * K_ + k] * w[k];
            b[l] = s;
        }
        float wb = 0.f, by = 0.f, btb = 0.f;
#pragma unroll
        for (int k = 0; k < K_; ++k) {
            wb += w[k] * b[k];
            by += b[k] * psm.sZ[pi * WST + k];
            float s = 0.f;
#pragma unroll
            for (int l = 0; l < K_; ++l) s += psm.sT[k * K_ + l] * b[l];
            btb += b[k] * s;
        }
        float v = NOISEF * (1.f + wb);
        float Q = psm.sC[pi * 65 + pi] - 2.f * by + btb;
        term = -0.5f * logf(v) - 0.5f * LOG2PI_F - 0.5f * Q / (v * (float)N_);
    }
    if (tid < 64) {
#pragma unroll
        for (int o = 16; o > 0; o >>= 1)
            term += __shfl_xor_sync(0xffffffffu, term, o);
        if ((tid & 31) == 0) psm.sred[tid >> 5] = term;
    }
    __syncthreads();
    if (tid == 0) {
        atomicAdd(&g_loss, (double)(psm.sred[0] + psm.sred[1]) / ((double)P_ * (double)m));
        __threadfence();
        unsigned d = atomicAdd(&g_done2, 1u);
        psm.slast = (d == (unsigned)(D_ * P_ - 1)) ? 1 : 0;
    }
    __syncthreads();

    if (psm.slast) {
        // finalize: write output, reset ALL state for the next graph replay
        for (int i = tid; i < D_ * D_; i += 256) g_Cf[i] = 0.f;
        if (tid == 0) {
            out[0] = -(float)g_loss;
            g_loss = 0.0;
            g_done  = 0u;
            g_done2 = 0u;
        }
    }
}

extern "C" void kernel_launch(void* const* d_in, const int* in_sizes, int n_in,
                              void* d_out, int out_size) {
    const float* x     = (const float*)d_in[0];
    const float* W     = (const float*)d_in[1];
    const int*   perms = (const int*)d_in[2];
    (void)in_sizes; (void)n_in; (void)out_size;

    k_fused<<<NBLK, 256>>>(x, W, perms, (float*)d_out);
}

// round 10
// speedup vs baseline: 1.7477x; 1.0210x over previous
#include <cuda_runtime.h>

#define D_      64
#define K_      16
#define N_      65536
#define P_      2
#define NOISEF  0.1f
#define LOG2PI_F 1.83787706640934534f

#define NBLK    296          // 2 CTAs x 148 SMs, all co-resident
#define TROWS   32
#define NTILES  (N_ / TROWS) // 2048
#define SXST    72           // padded row stride: 72 mod 32 = 8 -> conflict-free frags
#define WST     20           // padded row stride for 64x16 arrays

__device__ float    g_Cf[D_ * D_];
__device__ double   g_loss;
__device__ unsigned g_done;      // xtx-phase completion counter
__device__ unsigned g_done2;     // pairs-phase completion counter

__device__ __forceinline__ void cpasync16(unsigned smem, const void* g) {
    asm volatile("cp.async.cg.shared.global [%0], [%1], 16;\n" :: "r"(smem), "l"(g));
}
__device__ __forceinline__ void cp_commit() {
    asm volatile("cp.async.commit_group;\n" ::: "memory");
}
__device__ __forceinline__ void cp_wait2() {
    asm volatile("cp.async.wait_group 2;\n" ::: "memory");
}
__device__ __forceinline__ unsigned cvt_tf32(float f) {
    unsigned r;
    asm("cvt.rna.tf32.f32 %0, %1;" : "=r"(r) : "f"(f));
    return r;
}
__device__ __forceinline__ void mma_tf32(float& d0, float& d1, float& d2, float& d3,
                                         unsigned a0, unsigned a1, unsigned a2, unsigned a3,
                                         unsigned b0, unsigned b1) {
    asm("mma.sync.aligned.m16n8k8.row.col.f32.tf32.tf32.f32 "
        "{%0,%1,%2,%3}, {%4,%5,%6,%7}, {%8,%9}, {%0,%1,%2,%3};"
        : "+f"(d0), "+f"(d1), "+f"(d2), "+f"(d3)
        : "r"(a0), "r"(a1), "r"(a2), "r"(a3), "r"(b0), "r"(b1));
}
__device__ __forceinline__ unsigned ld_acq(unsigned* p) {
    unsigned v;
    asm volatile("ld.acquire.gpu.u32 %0, [%1];" : "=r"(v) : "l"(p) : "memory");
    return v;
}

struct XtxSmem {
    float sx[4][TROWS * SXST];   // 4-slot cp.async pipeline, 3 tiles in flight
};
struct PairsSmem {
    float sC[D_ * 65];
    float sW[D_ * WST];
    float sWm[D_ * WST];
    float sZ[D_ * WST];
    float sT[K_ * K_];
    float sG[K_ * K_];
    float sGi[K_ * K_];
    int   sperm[D_];
    int   spos[D_];
    float sred[2];
    int   slast;
};
#define SMEM_BYTES (sizeof(PairsSmem) > sizeof(XtxSmem) ? sizeof(PairsSmem) : sizeof(XtxSmem))

// ---------------------------------------------------------------------------
// Fused persistent kernel.
// Phase 1 (all 296 blocks): C = x^T x via tf32 mma.sync, 4-slot cp.async
// pipeline with 3 tiles in flight; 8 warps tile the 64x64 output.
// Phase 2: 128 pair tasks mapped to blocks {0..63} u {148..211} so each of
// 64 SMs hosts TWO pair CTAs (4 warps/SMSP -> latency hiding), per the
// classic-launch bid->smid map (bid and bid+148 share an SM).
// ---------------------------------------------------------------------------
__global__ __launch_bounds__(256, 2) void k_fused(const float* __restrict__ x,
                                                  const float* __restrict__ W,
                                                  const int* __restrict__ perms,
                                                  float* __restrict__ out) {
    __shared__ __align__(16) unsigned char smem_u[SMEM_BYTES];
    XtxSmem& xs = *reinterpret_cast<XtxSmem*>(smem_u);

    const int tid = threadIdx.x;

    // ---------------- Phase 1: tf32 MMA x^T x ----------------
    {
        const int w    = tid >> 5;
        const int lane = tid & 31;
        const int gid  = lane >> 2;       // 0..7
        const int tig  = lane & 3;        // 0..3
        const int ms   = (w >> 1) << 4;   // m-strip base: 0,16,32,48
        const int nh   = (w & 1) << 5;    // n-half base: 0,32

        float acc[4][4];
#pragma unroll
        for (int t = 0; t < 4; ++t)
#pragma unroll
            for (int q = 0; q < 4; ++q) acc[t][q] = 0.f;

        unsigned sb[4];
#pragma unroll
        for (int s = 0; s < 4; ++s)
            sb[s] = (unsigned)__cvta_generic_to_shared(&xs.sx[s][0]);

        // cp.async staging: 512 float4 per tile; f4 -> row=f4>>4, seg=f4&15
        const unsigned so0 = (unsigned)((tid >> 4) * SXST * 4 + (tid & 15) * 16);
        const unsigned so1 = (unsigned)(((tid + 256) >> 4) * SXST * 4 + (tid & 15) * 16);

        // prologue: prefetch 3 tiles into slots 0,1,2
#pragma unroll
        for (int s = 0; s < 3; ++s) {
            int tt = blockIdx.x + s * NBLK;
            if (tt < NTILES) {
                const float4* g4 = reinterpret_cast<const float4*>(x + (long long)tt * TROWS * 64);
                cpasync16(sb[s] + so0, g4 + tid);
                cpasync16(sb[s] + so1, g4 + tid + 256);
            }
            cp_commit();
        }

        int sidx = 0;
        for (int tile = blockIdx.x; tile < NTILES; tile += NBLK) {
            cp_wait2();           // oldest group (this tile) complete
            __syncthreads();      // slot (sidx+3)&3 free, slot sidx visible

            int pf = tile + 3 * NBLK;
            int ps = (sidx + 3) & 3;
            if (pf < NTILES) {
                const float4* g4 = reinterpret_cast<const float4*>(x + (long long)pf * TROWS * 64);
                cpasync16(sb[ps] + so0, g4 + tid);
                cpasync16(sb[ps] + so1, g4 + tid + 256);
            }
            cp_commit();

            const float* sxt = &xs.sx[sidx][0];
#pragma unroll
            for (int ks = 0; ks < 4; ++ks) {
                const float* r0 = sxt + (ks * 8 + tig) * SXST;
                const float* r4 = r0 + 4 * SXST;
                unsigned a0 = cvt_tf32(r0[ms + gid]);
                unsigned a1 = cvt_tf32(r0[ms + gid + 8]);
                unsigned a2 = cvt_tf32(r4[ms + gid]);
                unsigned a3 = cvt_tf32(r4[ms + gid + 8]);
#pragma unroll
                for (int t = 0; t < 4; ++t) {
                    int n0 = nh + t * 8;
                    unsigned b0 = cvt_tf32(r0[n0 + gid]);
                    unsigned b1 = cvt_tf32(r4[n0 + gid]);
                    mma_tf32(acc[t][0], acc[t][1], acc[t][2], acc[t][3],
                             a0, a1, a2, a3, b0, b1);
                }
            }
            sidx = (sidx + 1) & 3;
        }

        // flush accumulators (rows ms+gid / +8, cols n0+2tig / +1)
#pragma unroll
        for (int t = 0; t < 4; ++t) {
            int c0 = nh + t * 8 + 2 * tig;
            atomicAdd(&g_Cf[(ms + gid) * 64 + c0],     acc[t][0]);
            atomicAdd(&g_Cf[(ms + gid) * 64 + c0 + 1], acc[t][1]);
            atomicAdd(&g_Cf[(ms + gid + 8) * 64 + c0],     acc[t][2]);
            atomicAdd(&g_Cf[(ms + gid + 8) * 64 + c0 + 1], acc[t][3]);
        }
        __threadfence();
        __syncthreads();
        if (tid == 0) atomicAdd(&g_done, 1u);
    }

    // ---------------- Phase 2: Woodbury pairs ----------------
    // Task map: blocks {0..63} and {148..211} -> 2 pair CTAs per SM.
    int task;
    if (blockIdx.x < 64)                              task = blockIdx.x;
    else if (blockIdx.x >= 148 && blockIdx.x < 212)   task = 64 + (blockIdx.x - 148);
    else                                              return;

    if (tid == 0) {
        while (ld_acq(&g_done) < NBLK) __nanosleep(64);
    }
    __syncthreads();     // also fences the smem union switch

    PairsSmem& psm = *reinterpret_cast<PairsSmem*>(smem_u);

    const int a = task >> 1;
    const int m = a + 1;
    const int* perm = perms + (a * P_ + (task & 1)) * D_;

#pragma unroll
    for (int i = 0; i < 16; ++i) {
        int idx = tid + 256 * i;
        psm.sC[(idx >> 6) * 65 + (idx & 63)] = g_Cf[idx];
    }
    if (tid < D_) psm.sperm[tid] = perm[tid];
#pragma unroll
    for (int i = 0; i < 4; ++i) {
        int idx = tid + 256 * i;
        psm.sW[(idx >> 4) * WST + (idx & 15)] = W[idx];
    }
    __syncthreads();
    if (tid < D_) psm.spos[psm.sperm[tid]] = tid;
    __syncthreads();
#pragma unroll
    for (int i = 0; i < 4; ++i) {
        int idx = tid + 256 * i;
        int o = idx >> 4, k = idx & 15;
        psm.sWm[o * WST + k] = (psm.spos[o] >= m) ? psm.sW[o * WST + k] : 0.f;
    }
    __syncthreads();

    // G: one element per thread
    const int gk = tid >> 4, gl = tid & 15;
    {
        float s = (gk == gl) ? NOISEF : 0.f;
#pragma unroll
        for (int o = 0; o < D_; ++o)
            s += psm.sWm[o * WST + gk] * psm.sWm[o * WST + gl];
        psm.sG[gk * K_ + gl] = s;
    }
    // Z = C @ Wm
    {
        const int o = tid & 63, lb = (tid >> 6) << 2;
        float z0 = 0.f, z1 = 0.f, z2 = 0.f, z3 = 0.f;
#pragma unroll
        for (int j = 0; j < D_; ++j) {
            float c = psm.sC[o * 65 + j];
            const float4 wv = *reinterpret_cast<const float4*>(psm.sWm + j * WST + lb);
            z0 += c * wv.x; z1 += c * wv.y; z2 += c * wv.z; z3 += c * wv.w;
        }
        *reinterpret_cast<float4*>(psm.sZ + o * WST + lb) = make_float4(z0, z1, z2, z3);
    }
    __syncthreads();

    if (tid < 32) {
        // warp 0: shuffle Jordan inversion of 16x16 SPD G
        const int lane = tid;
        float col[K_];
#pragma unroll
        for (int r = 0; r < K_; ++r)
            col[r] = (lane < K_) ? psm.sG[r * K_ + lane]
                                 : ((r == lane - K_) ? 1.f : 0.f);
#pragma unroll
        for (int k = 0; k < K_; ++k) {
            float pv = __shfl_sync(0xffffffffu, col[k], k);
            float ip = 1.0f / pv;
            float ck = col[k];
#pragma unroll
            for (int r = 0; r < K_; ++r) {
                if (r != k) {
                    float mr = __shfl_sync(0xffffffffu, col[r], k) * ip;
                    col[r] -= mr * ck;
                }
            }
        }
        float own = 1.f;
#pragma unroll
        for (int r = 0; r < K_; ++r)
            if (r == lane) own = col[r];
        float oinv = 1.0f / own;
#pragma unroll
        for (int r = 0; r < K_; ++r) {
            float di = __shfl_sync(0xffffffffu, oinv, r);
            if (lane >= K_) psm.sGi[r * K_ + (lane - K_)] = col[r] * di;
        }
    } else {
        // warps 1-7: T = Wm^T Z
        for (int it = tid - 32; it < 256; it += 224) {
            int k = it >> 4, l = it & 15;
            float s = 0.f;
#pragma unroll
            for (int o = 0; o < D_; ++o)
                s += psm.sWm[o * WST + k] * psm.sZ[o * WST + l];
            psm.sT[k * K_ + l] = s;
        }
    }
    __syncthreads();

    // per-row terms
    float term = 0.f;
    if (tid < m) {
        const int pi = psm.sperm[tid];
        float w[K_], b[K_];
#pragma unroll
        for (int k4 = 0; k4 < K_; k4 += 4) {
            const float4 wv = *reinterpret_cast<const float4*>(psm.sW + pi * WST + k4);
            w[k4] = wv.x; w[k4 + 1] = wv.y; w[k4 + 2] = wv.z; w[k4 + 3] = wv.w;
        }
#pragma unroll
        for (int l = 0; l < K_; ++l) {
            float s = 0.f;
#pragma unroll
            for (int k = 0; k < K_; ++k) s += psm.sGi[l * K_ + k] * w[k];
            b[l] = s;
        }
        float wb = 0.f, by = 0.f, btb = 0.f;
#pragma unroll
        for (int k = 0; k < K_; ++k) {
            wb += w[k] * b[k];
            by += b[k] * psm.sZ[pi * WST + k];
            float s = 0.f;
#pragma unroll
            for (int l = 0; l < K_; ++l) s += psm.sT[k * K_ + l] * b[l];
            btb += b[k] * s;
        }
        float v = NOISEF * (1.f + wb);
        float Q = psm.sC[pi * 65 + pi] - 2.f * by + btb;
        term = -0.5f * logf(v) - 0.5f * LOG2PI_F - 0.5f * Q / (v * (float)N_);
    }
    if (tid < 64) {
#pragma unroll
        for (int o = 16; o > 0; o >>= 1)
            term += __shfl_xor_sync(0xffffffffu, term, o);
        if ((tid & 31) == 0) psm.sred[tid >> 5] = term;
    }
    __syncthreads();
    if (tid == 0) {
        atomicAdd(&g_loss, (double)(psm.sred[0] + psm.sred[1]) / ((double)P_ * (double)m));
        __threadfence();
        unsigned d = atomicAdd(&g_done2, 1u);
        psm.slast = (d == (unsigned)(D_ * P_ - 1)) ? 1 : 0;
    }
    __syncthreads();

    if (psm.slast) {
        // finalize: write output, reset ALL state for the next graph replay
        for (int i = tid; i < D_ * D_; i += 256) g_Cf[i] = 0.f;
        if (tid == 0) {
            out[0] = -(float)g_loss;
            g_loss = 0.0;
            g_done  = 0u;
            g_done2 = 0u;
        }
    }
}

extern "C" void kernel_launch(void* const* d_in, const int* in_sizes, int n_in,
                              void* d_out, int out_size) {
    const float* x     = (const float*)d_in[0];
    const float* W     = (const float*)d_in[1];
    const int*   perms = (const int*)d_in[2];
    (void)in_sizes; (void)n_in; (void)out_size;

    k_fused<<<NBLK, 256>>>(x, W, perms, (float*)d_out);
}

// round 11
// speedup vs baseline: 1.7662x; 1.0106x over previous
#include <cuda_runtime.h>

#define D_      64
#define K_      16
#define N_      65536
#define P_      2
#define NOISEF  0.1f
#define LOG2PI_F 1.83787706640934534f

#define NBLK    296          // 2 CTAs x 148 SMs, all co-resident
#define TROWS   32
#define NTILES  (N_ / TROWS) // 2048
#define SXST    72           // padded row stride: conflict-free fragment LDS
#define WST     20           // padded row stride for 64x16 arrays

__device__ float    g_Cf[D_ * D_];
__device__ double   g_loss;
__device__ unsigned g_done;      // xtx-phase completion counter
__device__ unsigned g_done2;     // pairs-phase completion counter

__device__ __forceinline__ void cpasync16(unsigned smem, const void* g) {
    asm volatile("cp.async.cg.shared.global [%0], [%1], 16;\n" :: "r"(smem), "l"(g));
}
__device__ __forceinline__ void cp_commit() {
    asm volatile("cp.async.commit_group;\n" ::: "memory");
}
__device__ __forceinline__ void cp_wait2() {
    asm volatile("cp.async.wait_group 2;\n" ::: "memory");
}
__device__ __forceinline__ unsigned cvt_tf32(float f) {
    unsigned r;
    asm("cvt.rna.tf32.f32 %0, %1;" : "=r"(r) : "f"(f));
    return r;
}
__device__ __forceinline__ void mma_tf32(float& d0, float& d1, float& d2, float& d3,
                                         unsigned a0, unsigned a1, unsigned a2, unsigned a3,
                                         unsigned b0, unsigned b1) {
    asm("mma.sync.aligned.m16n8k8.row.col.f32.tf32.tf32.f32 "
        "{%0,%1,%2,%3}, {%4,%5,%6,%7}, {%8,%9}, {%0,%1,%2,%3};"
        : "+f"(d0), "+f"(d1), "+f"(d2), "+f"(d3)
        : "r"(a0), "r"(a1), "r"(a2), "r"(a3), "r"(b0), "r"(b1));
}
__device__ __forceinline__ unsigned ld_acq(unsigned* p) {
    unsigned v;
    asm volatile("ld.acquire.gpu.u32 %0, [%1];" : "=r"(v) : "l"(p) : "memory");
    return v;
}

// ---------------------------------------------------------------------------
// Fused persistent kernel.
// Phase 1 (all 296 blocks): C = x^T x via tf32 mma.sync + 4-slot cp.async.
// Prep (pair blocks, BEFORE the device barrier, overlapped with phase 1 of
// the other blocks): perm, pos, Wm, G = 0.1I + Wm^T Wm, Gi (warp-shuffle
// Jordan). Only the C-dependent remainder (load C, Z, T, terms) runs after
// the spin. Prep smem lives outside the xtx tile-buffer union.
// ---------------------------------------------------------------------------
__global__ __launch_bounds__(256, 2) void k_fused(const float* __restrict__ x,
                                                  const float* __restrict__ W,
                                                  const int* __restrict__ perms,
                                                  float* __restrict__ out) {
    // union region: xtx tiles (9216 floats) / pairs sC(4160)+sZ(1280)+sT(256)
    __shared__ __align__(16) float s_sx[4 * TROWS * SXST];
    // prep region (survives across the phase switch)
    __shared__ __align__(16) float s_wm[D_ * WST];
    __shared__ float s_g[K_ * K_];
    __shared__ float s_gi[K_ * K_];
    __shared__ int   s_perm[D_];
    __shared__ int   s_pos[D_];
    __shared__ float s_red[2];
    __shared__ int   s_last;

    const int tid = threadIdx.x;

    // ---------------- Phase 1: tf32 MMA x^T x ----------------
    {
        const int w    = tid >> 5;
        const int lane = tid & 31;
        const int gid  = lane >> 2;       // 0..7
        const int tig  = lane & 3;        // 0..3
        const int ms   = (w >> 1) << 4;   // m-strip base: 0,16,32,48
        const int nh   = (w & 1) << 5;    // n-half base: 0,32

        float acc[4][4];
#pragma unroll
        for (int t = 0; t < 4; ++t)
#pragma unroll
            for (int q = 0; q < 4; ++q) acc[t][q] = 0.f;

        unsigned sb[4];
#pragma unroll
        for (int s = 0; s < 4; ++s)
            sb[s] = (unsigned)__cvta_generic_to_shared(&s_sx[s * TROWS * SXST]);

        const unsigned so0 = (unsigned)((tid >> 4) * SXST * 4 + (tid & 15) * 16);
        const unsigned so1 = (unsigned)(((tid + 256) >> 4) * SXST * 4 + (tid & 15) * 16);

        // prologue: prefetch 3 tiles into slots 0,1,2
#pragma unroll
        for (int s = 0; s < 3; ++s) {
            int tt = blockIdx.x + s * NBLK;
            if (tt < NTILES) {
                const float4* g4 = reinterpret_cast<const float4*>(x + (long long)tt * TROWS * 64);
                cpasync16(sb[s] + so0, g4 + tid);
                cpasync16(sb[s] + so1, g4 + tid + 256);
            }
            cp_commit();
        }

        int sidx = 0;
        for (int tile = blockIdx.x; tile < NTILES; tile += NBLK) {
            cp_wait2();           // oldest group (this tile) complete
            __syncthreads();      // slot (sidx+3)&3 free, slot sidx visible

            int pf = tile + 3 * NBLK;
            int ps = (sidx + 3) & 3;
            if (pf < NTILES) {
                const float4* g4 = reinterpret_cast<const float4*>(x + (long long)pf * TROWS * 64);
                cpasync16(sb[ps] + so0, g4 + tid);
                cpasync16(sb[ps] + so1, g4 + tid + 256);
            }
            cp_commit();

            const float* sxt = &s_sx[sidx * TROWS * SXST];
#pragma unroll
            for (int ks = 0; ks < 4; ++ks) {
                const float* r0 = sxt + (ks * 8 + tig) * SXST;
                const float* r4 = r0 + 4 * SXST;
                unsigned a0 = cvt_tf32(r0[ms + gid]);
                unsigned a1 = cvt_tf32(r0[ms + gid + 8]);
                unsigned a2 = cvt_tf32(r4[ms + gid]);
                unsigned a3 = cvt_tf32(r4[ms + gid + 8]);
#pragma unroll
                for (int t = 0; t < 4; ++t) {
                    int n0 = nh + t * 8;
                    unsigned b0 = cvt_tf32(r0[n0 + gid]);
                    unsigned b1 = cvt_tf32(r4[n0 + gid]);
                    mma_tf32(acc[t][0], acc[t][1], acc[t][2], acc[t][3],
                             a0, a1, a2, a3, b0, b1);
                }
            }
            sidx = (sidx + 1) & 3;
        }

        // flush accumulators (rows ms+gid / +8, cols n0+2tig / +1)
#pragma unroll
        for (int t = 0; t < 4; ++t) {
            int c0 = nh + t * 8 + 2 * tig;
            atomicAdd(&g_Cf[(ms + gid) * 64 + c0],     acc[t][0]);
            atomicAdd(&g_Cf[(ms + gid) * 64 + c0 + 1], acc[t][1]);
            atomicAdd(&g_Cf[(ms + gid + 8) * 64 + c0],     acc[t][2]);
            atomicAdd(&g_Cf[(ms + gid + 8) * 64 + c0 + 1], acc[t][3]);
        }
        __threadfence();
        __syncthreads();
        if (tid == 0) atomicAdd(&g_done, 1u);
    }

    // ---------------- Pair-task selection ----------------
    // Blocks {0..63} and {148..211} -> 2 pair CTAs per SM (classic map).
    int task;
    if (blockIdx.x < 64)                              task = blockIdx.x;
    else if (blockIdx.x >= 148 && blockIdx.x < 212)   task = 64 + (blockIdx.x - 148);
    else                                              return;

    const int a = task >> 1;
    const int m = a + 1;
    const int* perm = perms + (a * P_ + (task & 1)) * D_;

    // ---------------- Prep: C-independent work, overlapped with phase 1 ----
    if (tid < D_) s_perm[tid] = perm[tid];
    __syncthreads();
    if (tid < D_) s_pos[s_perm[tid]] = tid;
    __syncthreads();
#pragma unroll
    for (int i = 0; i < 4; ++i) {
        int idx = tid + 256 * i;
        int o = idx >> 4, k = idx & 15;
        float wv = W[idx];
        s_wm[o * WST + k] = (s_pos[o] >= m) ? wv : 0.f;
    }
    __syncthreads();

    const int gk = tid >> 4, gl = tid & 15;
    {
        float s = (gk == gl) ? NOISEF : 0.f;
#pragma unroll
        for (int o = 0; o < D_; ++o)
            s += s_wm[o * WST + gk] * s_wm[o * WST + gl];
        s_g[gk * K_ + gl] = s;
    }
    __syncthreads();

    if (tid < 32) {
        // warp 0: shuffle Jordan inversion of 16x16 SPD G
        const int lane = tid;
        float col[K_];
#pragma unroll
        for (int r = 0; r < K_; ++r)
            col[r] = (lane < K_) ? s_g[r * K_ + lane]
                                 : ((r == lane - K_) ? 1.f : 0.f);
#pragma unroll
        for (int k = 0; k < K_; ++k) {
            float pv = __shfl_sync(0xffffffffu, col[k], k);
            float ip = 1.0f / pv;
            float ck = col[k];
#pragma unroll
            for (int r = 0; r < K_; ++r) {
                if (r != k) {
                    float mr = __shfl_sync(0xffffffffu, col[r], k) * ip;
                    col[r] -= mr * ck;
                }
            }
        }
        float own = 1.f;
#pragma unroll
        for (int r = 0; r < K_; ++r)
            if (r == lane) own = col[r];
        float oinv = 1.0f / own;
#pragma unroll
        for (int r = 0; r < K_; ++r) {
            float di = __shfl_sync(0xffffffffu, oinv, r);
            if (lane >= K_) s_gi[r * K_ + (lane - K_)] = col[r] * di;
        }
    }

    // ---------------- Wait for C ----------------
    if (tid == 0) {
        while (ld_acq(&g_done) < NBLK) __nanosleep(64);
    }
    __syncthreads();     // release barrier: s_gi visible, smem union switch

    float* sC = s_sx;            // 64 x 65
    float* sZ = s_sx + 4160;     // 64 x WST
    float* sT = s_sx + 5440;     // 16 x 16

    // ---------------- C-dependent remainder ----------------
#pragma unroll
    for (int i = 0; i < 16; ++i) {
        int idx = tid + 256 * i;
        sC[(idx >> 6) * 65 + (idx & 63)] = g_Cf[idx];
    }
    __syncthreads();

    // Z = C @ Wm
    {
        const int o = tid & 63, lb = (tid >> 6) << 2;
        float z0 = 0.f, z1 = 0.f, z2 = 0.f, z3 = 0.f;
#pragma unroll
        for (int j = 0; j < D_; ++j) {
            float c = sC[o * 65 + j];
            const float4 wv = *reinterpret_cast<const float4*>(s_wm + j * WST + lb);
            z0 += c * wv.x; z1 += c * wv.y; z2 += c * wv.z; z3 += c * wv.w;
        }
        *reinterpret_cast<float4*>(sZ + o * WST + lb) = make_float4(z0, z1, z2, z3);
    }
    __syncthreads();

    // T = Wm^T Z : one element per thread (256 = 16x16)
    {
        float s = 0.f;
#pragma unroll
        for (int o = 0; o < D_; ++o)
            s += s_wm[o * WST + gk] * sZ[o * WST + gl];
        sT[gk * K_ + gl] = s;
    }
    __syncthreads();

    // per-row terms
    float term = 0.f;
    if (tid < m) {
        const int pi = s_perm[tid];
        float w[K_], b[K_];
#pragma unroll
        for (int k4 = 0; k4 < K_; k4 += 4) {
            const float4 wv = *reinterpret_cast<const float4*>(W + pi * K_ + k4);
            w[k4] = wv.x; w[k4 + 1] = wv.y; w[k4 + 2] = wv.z; w[k4 + 3] = wv.w;
        }
#pragma unroll
        for (int l = 0; l < K_; ++l) {
            float s = 0.f;
#pragma unroll
            for (int k = 0; k < K_; ++k) s += s_gi[l * K_ + k] * w[k];
            b[l] = s;
        }
        float wb = 0.f, by = 0.f, btb = 0.f;
#pragma unroll
        for (int k = 0; k < K_; ++k) {
            wb += w[k] * b[k];
            by += b[k] * sZ[pi * WST + k];
            float s = 0.f;
#pragma unroll
            for (int l = 0; l < K_; ++l) s += sT[k * K_ + l] * b[l];
            btb += b[k] * s;
        }
        float v = NOISEF * (1.f + wb);
        float Q = sC[pi * 65 + pi] - 2.f * by + btb;
        term = -0.5f * logf(v) - 0.5f * LOG2PI_F - 0.5f * Q / (v * (float)N_);
    }
    if (tid < 64) {
#pragma unroll
        for (int o = 16; o > 0; o >>= 1)
            term += __shfl_xor_sync(0xffffffffu, term, o);
        if ((tid & 31) == 0) s_red[tid >> 5] = term;
    }
    __syncthreads();
    if (tid == 0) {
        atomicAdd(&g_loss, (double)(s_red[0] + s_red[1]) / ((double)P_ * (double)m));
        __threadfence();
        unsigned d = atomicAdd(&g_done2, 1u);
        s_last = (d == (unsigned)(D_ * P_ - 1)) ? 1 : 0;
    }
    __syncthreads();

    if (s_last) {
        // finalize: write output, reset ALL state for the next graph replay
        for (int i = tid; i < D_ * D_; i += 256) g_Cf[i] = 0.f;
        if (tid == 0) {
            out[0] = -(float)g_loss;
            g_loss = 0.0;
            g_done  = 0u;
            g_done2 = 0u;
        }
    }
}

extern "C" void kernel_launch(void* const* d_in, const int* in_sizes, int n_in,
                              void* d_out, int out_size) {
    const float* x     = (const float*)d_in[0];
    const float* W     = (const float*)d_in[1];
    const int*   perms = (const int*)d_in[2];
    (void)in_sizes; (void)n_in; (void)out_size;

    k_fused<<<NBLK, 256>>>(x, W, perms, (float*)d_out);
}